// round 10
// baseline (speedup 1.0000x reference)
#include <cuda_runtime.h>
#include <math.h>

#define NPIX   784
#define NPOS   676
#define NCH    8
#define NCLS   10
#define FLATK  5408
#define THREADS 128
#define IMGB   4

// Tree max over the 9-pixel window for one image (field F of float4),
// all operands in registers — no pointer indexing into register arrays.
#define FZ_FIELD(F)                                                        \
    ({                                                                     \
        float a0 = q[0].F + w[0];                                          \
        float a1 = q[1].F + w[1];                                          \
        float a2 = q[2].F + w[2];                                          \
        float a3 = q[3].F + w[3];                                          \
        float a4 = q[4].F + w[4];                                          \
        float a5 = q[5].F + w[5];                                          \
        float a6 = q[6].F + w[6];                                          \
        float a7 = q[7].F + w[7];                                          \
        float a8 = q[8].F + w[8];                                          \
        float b0 = fmaxf(a0, a1);                                          \
        float b1 = fmaxf(a2, a3);                                          \
        float b2 = fmaxf(a4, a5);                                          \
        float b3 = fmaxf(a6, a7);                                          \
        fmaxf(fmaxf(fmaxf(fmaxf(b0, b1), fmaxf(b2, b3)), a8), 0.0f);       \
    })

__device__ __forceinline__ void prefetch_l1(const float* p) {
    asm volatile("prefetch.global.L1 [%0];" :: "l"(p));
}

__global__ __launch_bounds__(THREADS, 4)
void fused_afrnn_kernel(const float* __restrict__ x,
                        const float* __restrict__ wfuzzy,
                        const float* __restrict__ wdense,
                        float* __restrict__ out)
{
    __shared__ float4 sx4[NPIX];        // {im0..im3} per pixel, 12.5 KB
    __shared__ float4 swf[NCH * 3];     // (w-1) padded rows
    __shared__ float  red[4][IMGB * NCLS];
    __shared__ float  tot[IMGB * NCLS];

    const int tid  = threadIdx.x;
    const int lane = tid & 31;
    const int img0 = blockIdx.x * IMGB;

    // Per-thread prefetch offsets: lane v-th slot covers weight line (c,o)
    // with idx = lane + 32v.  Each (c,o) line = 128B = the 32 consecutive p
    // this warp owns.  3 slots x 32 lanes = 96 >= 80 lines; extras clamp to 0.
    int off0, off1, off2;
    {
        int i0 = lane;           // 0..31  -> always valid (< 80)
        int i1 = lane + 32;      // 32..63 -> valid
        int i2 = lane + 64;      // 64..95 -> valid if < 80
        off0 = (i0 % NCLS) * FLATK + (i0 / NCLS) * NPOS;
        off1 = (i1 % NCLS) * FLATK + (i1 / NCLS) * NPOS;
        off2 = (i2 < 80) ? (i2 % NCLS) * FLATK + (i2 / NCLS) * NPOS : off0;
    }

    // ---- stage: transpose 4 images into interleaved smem ----
    {
        float* sxs = (float*)sx4;
        const float* x0 = x + (size_t)img0 * NPIX;
        for (int idx = tid; idx < IMGB * NPIX; idx += THREADS) {
            int im  = idx / NPIX;
            int pix = idx - im * NPIX;
            sxs[pix * 4 + im] = x0[idx];
        }
        if (tid < NCH * 3) {
            int c = tid / 3, j = tid - c * 3;
            float v[4];
            #pragma unroll
            for (int k = 0; k < 4; k++) {
                int o = j * 4 + k;
                v[k] = (o < 9) ? (wfuzzy[c * 9 + o] - 1.0f) : 0.0f;
            }
            swf[tid] = make_float4(v[0], v[1], v[2], v[3]);
        }
    }

    // Prologue: prefetch the FIRST p-step's 80 weight lines while staging drains.
    {
        const float* wbase0 = wdense + (tid - lane);   // warp's first-line base
        prefetch_l1(wbase0 + off0);
        prefetch_l1(wbase0 + off1);
        prefetch_l1(wbase0 + off2);
    }
    __syncthreads();

    float acc[IMGB][NCLS];
    #pragma unroll
    for (int im = 0; im < IMGB; im++)
        #pragma unroll
        for (int o = 0; o < NCLS; o++) acc[im][o] = 0.0f;

    for (int p = tid; p < NPOS; p += THREADS) {
        // Prefetch NEXT p-step's weight lines into L1 (3 instrs cover 80 lines).
        const int pn = p + THREADS;
        if (pn - lane < NPOS) {                     // uniform per warp
            const float* wbn = wdense + (pn - lane);
            prefetch_l1(wbn + off0);
            prefetch_l1(wbn + off1);
            prefetch_l1(wbn + off2);
        }

        const int i    = p / 26;
        const int j    = p - i * 26;
        const int base = i * 28 + j;

        // 3x3 window x 4 images: 9 LDS.128, conflict-free
        float4 q[9];
        #pragma unroll
        for (int r = 0; r < 3; r++)
            #pragma unroll
            for (int cc = 0; cc < 3; cc++)
                q[r * 3 + cc] = sx4[base + r * 28 + cc];

        const float* wcol0 = wdense + p;

        #pragma unroll
        for (int c = 0; c < NCH; c++) {
            // dense weights: 10 coalesced scalar LDG (L1-hot via prefetch)
            const float* wcol = wcol0 + c * NPOS;
            float wv[NCLS];
            #pragma unroll
            for (int o = 0; o < NCLS; o++)
                wv[o] = __ldg(wcol + o * FLATK);

            // fuzzy weights (w-1): 3 broadcast LDS.128
            const float4 wA = swf[c * 3 + 0];
            const float4 wB = swf[c * 3 + 1];
            const float4 wC = swf[c * 3 + 2];
            const float w[9] = { wA.x, wA.y, wA.z, wA.w,
                                 wB.x, wB.y, wB.z, wB.w, wC.x };

            const float fz0 = FZ_FIELD(x);
            const float fz1 = FZ_FIELD(y);
            const float fz2 = FZ_FIELD(z);
            const float fz3 = FZ_FIELD(w);

            #pragma unroll
            for (int o = 0; o < NCLS; o++) {
                acc[0][o] = fmaf(fz0, wv[o], acc[0][o]);
                acc[1][o] = fmaf(fz1, wv[o], acc[1][o]);
                acc[2][o] = fmaf(fz2, wv[o], acc[2][o]);
                acc[3][o] = fmaf(fz3, wv[o], acc[3][o]);
            }
        }
    }

    // ---- reduce partial logits across the block ----
    const int wid = tid >> 5;
    #pragma unroll
    for (int im = 0; im < IMGB; im++) {
        #pragma unroll
        for (int o = 0; o < NCLS; o++) {
            float t = acc[im][o];
            t += __shfl_down_sync(0xffffffffu, t, 16);
            t += __shfl_down_sync(0xffffffffu, t, 8);
            t += __shfl_down_sync(0xffffffffu, t, 4);
            t += __shfl_down_sync(0xffffffffu, t, 2);
            t += __shfl_down_sync(0xffffffffu, t, 1);
            if (lane == 0) red[wid][im * NCLS + o] = t;
        }
    }
    __syncthreads();

    if (tid < IMGB * NCLS)
        tot[tid] = red[0][tid] + red[1][tid] + red[2][tid] + red[3][tid];
    __syncthreads();

    // ---- log_softmax (1 thread per image) ----
    if (tid < IMGB) {
        float l[NCLS];
        float mx = -1e30f;
        #pragma unroll
        for (int o = 0; o < NCLS; o++) {
            l[o] = tot[tid * NCLS + o];
            mx = fmaxf(mx, l[o]);
        }
        float s = 0.0f;
        #pragma unroll
        for (int o = 0; o < NCLS; o++) s += expf(l[o] - mx);
        const float lse = mx + logf(s);
        float* op = out + (size_t)(img0 + tid) * NCLS;
        #pragma unroll
        for (int o = 0; o < NCLS; o++) op[o] = l[o] - lse;
    }
}

extern "C" void kernel_launch(void* const* d_in, const int* in_sizes, int n_in,
                              void* d_out, int out_size)
{
    const float* x  = (const float*)d_in[0];   // (4096,1,28,28) fp32
    const float* wf = (const float*)d_in[1];   // (8,1,3,3)      fp32
    const float* wd = (const float*)d_in[2];   // (10,5408)      fp32
    float* out = (float*)d_out;                // (4096,10)      fp32

    const int nimg = in_sizes[0] / NPIX;       // 4096
    fused_afrnn_kernel<<<nimg / IMGB, THREADS>>>(x, wf, wd, out);
}